// round 4
// baseline (speedup 1.0000x reference)
#include <cuda_runtime.h>

#define T_STEPS 4
#define B_ 32
#define N_ 196
#define D_ 768
#define H_ 3072
#define BN_ (B_ * N_)          /* 6272  */
#define ROWS (T_STEPS * BN_)   /* 25088 */

// Scratch (static device globals: allocation-free per harness rules)
__device__ float g_h[(size_t)ROWS * H_];  // 308 MB: fc1 out, then spikes s1 in-place
__device__ float g_y[(size_t)ROWS * D_];  // 77 MB : fc2 out

// ---------------- packed f32x2 helpers (full-rate fp32 on sm_103a) ----------
__device__ __forceinline__ unsigned long long pack2(float lo, float hi) {
    unsigned long long r;
    asm("mov.b64 %0, {%1, %2};" : "=l"(r) : "f"(lo), "f"(hi));
    return r;
}
__device__ __forceinline__ void fma2(unsigned long long& d,
                                     unsigned long long a,
                                     unsigned long long b) {
    asm("fma.rn.f32x2 %0, %1, %2, %0;" : "+l"(d) : "l"(a), "l"(b));
}
__device__ __forceinline__ float2 unpack2(unsigned long long v) {
    float2 r;
    asm("mov.b64 {%0, %1}, %2;" : "=f"(r.x), "=f"(r.y) : "l"(v));
    return r;
}

// ---------------- GEMM: C[M,N] = A[M,K] @ B[N,K]^T + bias ------------------
// Both operands K-contiguous ("NT"). All of M,N multiples of 128; K of 16.
__global__ __launch_bounds__(256, 2)
void gemm_nt_bias(const float* __restrict__ A, const float* __restrict__ Bm,
                  const float* __restrict__ bias, float* __restrict__ C,
                  int M, int N, int K)
{
    __shared__ __align__(16) float As[16][132];
    __shared__ __align__(16) float Bs[16][132];

    const int t  = threadIdx.x;
    const int m0 = blockIdx.y * 128;
    const int n0 = blockIdx.x * 128;
    const int tx = t & 15;       // n sub-tile
    const int ty = t >> 4;       // m sub-tile
    const int NK = K >> 4;

    // each thread loads 2 float4 per operand per k-tile
    const int row = t >> 2;            // 0..63 (and row+64)
    const int kq  = (t & 3) * 4;       // 0,4,8,12

    float4 ra0, ra1, rb0, rb1;

    const float* Ap0 = A  + (size_t)(m0 + row) * K + kq;
    const float* Ap1 = Ap0 + (size_t)64 * K;
    const float* Bp0 = Bm + (size_t)(n0 + row) * K + kq;
    const float* Bp1 = Bp0 + (size_t)64 * K;

#define FETCH(KT) do {                                      \
        ra0 = *(const float4*)(Ap0 + (KT) * 16);            \
        ra1 = *(const float4*)(Ap1 + (KT) * 16);            \
        rb0 = *(const float4*)(Bp0 + (KT) * 16);            \
        rb1 = *(const float4*)(Bp1 + (KT) * 16);            \
    } while (0)

#define STORE_SMEM() do {                                                   \
        As[kq+0][row]    = ra0.x; As[kq+1][row]    = ra0.y;                 \
        As[kq+2][row]    = ra0.z; As[kq+3][row]    = ra0.w;                 \
        As[kq+0][row+64] = ra1.x; As[kq+1][row+64] = ra1.y;                 \
        As[kq+2][row+64] = ra1.z; As[kq+3][row+64] = ra1.w;                 \
        Bs[kq+0][row]    = rb0.x; Bs[kq+1][row]    = rb0.y;                 \
        Bs[kq+2][row]    = rb0.z; Bs[kq+3][row]    = rb0.w;                 \
        Bs[kq+0][row+64] = rb1.x; Bs[kq+1][row+64] = rb1.y;                 \
        Bs[kq+2][row+64] = rb1.z; Bs[kq+3][row+64] = rb1.w;                 \
    } while (0)

    FETCH(0);
    STORE_SMEM();
    __syncthreads();

    unsigned long long acc[4][8];
#pragma unroll
    for (int mi = 0; mi < 4; mi++)
#pragma unroll
        for (int j = 0; j < 8; j++) acc[mi][j] = 0ull;

    for (int kt = 0; kt < NK; kt++) {
        if (kt + 1 < NK) FETCH(kt + 1);

#pragma unroll
        for (int k = 0; k < 16; k++) {
            float4 a0 = *(const float4*)&As[k][ty * 8];
            float4 a1 = *(const float4*)&As[k][ty * 8 + 4];
            float4 b0 = *(const float4*)&Bs[k][tx * 8];
            float4 b1 = *(const float4*)&Bs[k][tx * 8 + 4];

            unsigned long long am[4];
            am[0] = pack2(a0.x, a0.y);
            am[1] = pack2(a0.z, a0.w);
            am[2] = pack2(a1.x, a1.y);
            am[3] = pack2(a1.z, a1.w);

            float bj[8] = {b0.x, b0.y, b0.z, b0.w, b1.x, b1.y, b1.z, b1.w};
#pragma unroll
            for (int j = 0; j < 8; j++) {
                unsigned long long bd = pack2(bj[j], bj[j]);
#pragma unroll
                for (int mi = 0; mi < 4; mi++) fma2(acc[mi][j], am[mi], bd);
            }
        }
        __syncthreads();
        if (kt + 1 < NK) STORE_SMEM();
        __syncthreads();
    }

    // epilogue
    float bb[8];
#pragma unroll
    for (int j = 0; j < 8; j++) bb[j] = bias[n0 + tx * 8 + j];

#pragma unroll
    for (int mi = 0; mi < 4; mi++) {
        const int m = m0 + ty * 8 + 2 * mi;
#pragma unroll
        for (int j = 0; j < 8; j++) {
            float2 c = unpack2(acc[mi][j]);
            size_t base = (size_t)m * N + n0 + tx * 8 + j;
            C[base]     = c.x + bb[j];
            C[base + N] = c.y + bb[j];
        }
    }
#undef FETCH
#undef STORE_SMEM
}

// ---------------- LIF scan over T=4 (vectorized float4) --------------------
// layout (T, plane): t-stride = plane elements. in==out allowed (in-place).
__device__ __forceinline__ void lif_step(float& v, float x, float& s) {
    v = v + (x - v) * 0.5f;          // matches reference: v + (x - v)/tau
    if (v >= 1.0f) { s = 1.0f; v = 0.0f; }
    else           { s = 0.0f; }
}

__global__ void lif4_kernel(const float4* __restrict__ in,
                            float4* __restrict__ out, int plane4)
{
    int i = blockIdx.x * blockDim.x + threadIdx.x;
    if (i >= plane4) return;
    float4 v = make_float4(0.f, 0.f, 0.f, 0.f);
#pragma unroll
    for (int t = 0; t < T_STEPS; t++) {
        float4 x = in[(size_t)t * plane4 + i];
        float4 s;
        lif_step(v.x, x.x, s.x);
        lif_step(v.y, x.y, s.y);
        lif_step(v.z, x.z, s.z);
        lif_step(v.w, x.w, s.w);
        out[(size_t)t * plane4 + i] = s;
    }
}

// ---------------------------------------------------------------------------
extern "C" void kernel_launch(void* const* d_in, const int* in_sizes, int n_in,
                              void* d_out, int out_size)
{
    const float* x  = (const float*)d_in[0];
    const float* W1 = (const float*)d_in[1];
    const float* b1 = (const float*)d_in[2];
    const float* W2 = (const float*)d_in[3];
    const float* b2 = (const float*)d_in[4];
    float* out = (float*)d_out;

    float *h, *y;
    cudaGetSymbolAddress((void**)&h, g_h);
    cudaGetSymbolAddress((void**)&y, g_y);

    // fc1: h = x @ W1^T + b1      (M=25088, N=3072, K=768)
    gemm_nt_bias<<<dim3(H_ / 128, ROWS / 128), 256>>>(x, W1, b1, h, ROWS, H_, D_);

    // LIF1 in-place on h -> binary spikes (fp32 0/1)
    {
        int plane4 = BN_ * H_ / 4;   // 4,816,896
        lif4_kernel<<<(plane4 + 255) / 256, 256>>>((const float4*)h, (float4*)h, plane4);
    }

    // fc2: y = s1 @ W2^T + b2     (M=25088, N=768, K=3072)
    gemm_nt_bias<<<dim3(D_ / 128, ROWS / 128), 256>>>(h, W2, b2, y, ROWS, D_, H_);

    // LIF2: y -> d_out
    {
        int plane4 = BN_ * D_ / 4;   // 1,204,224
        lif4_kernel<<<(plane4 + 255) / 256, 256>>>((const float4*)y, (float4*)out, plane4);
    }
}

// round 7
// speedup vs baseline: 1.1321x; 1.1321x over previous
#include <cuda_runtime.h>
#include <cuda_bf16.h>
#include <cstdint>

#define T_STEPS 4
#define BN_     6272
#define ROWS_   25088
#define D_      768
#define H_      3072
#define EPS_    1e-3f
#define CAP_    (1u << 20)

// ---------------- scratch (static device globals; no allocations) ----------
__device__ __nv_bfloat16 g_x0[(size_t)ROWS_ * D_];
__device__ __nv_bfloat16 g_x1[(size_t)ROWS_ * D_];
__device__ __nv_bfloat16 g_w1p[2][(size_t)H_ * D_];
__device__ __nv_bfloat16 g_w2p[2][(size_t)D_ * H_];
__device__ float         g_hf[(size_t)ROWS_ * H_];   // fc1 out fp32 (308MB)
__device__ __nv_bfloat16 g_s1[(size_t)ROWS_ * H_];   // LIF1 spikes bf16 (exact)
__device__ float         g_yf[(size_t)ROWS_ * D_];   // fc2 out fp32
__device__ unsigned      g_cnt[2];
__device__ unsigned      g_list1[CAP_];
__device__ unsigned      g_list2[CAP_];

// ---------------- PTX helpers (all sm_80-class: compile under sm_103) ------
__device__ __forceinline__ uint32_t smem_u32(const void* p) {
    uint32_t a;
    asm("{ .reg .u64 t; cvta.to.shared.u64 t, %1; cvt.u32.u64 %0, t; }"
        : "=r"(a) : "l"(p));
    return a;
}
#define CP_ASYNC16(dst, src) \
    asm volatile("cp.async.ca.shared.global [%0], [%1], 16;" :: "r"(dst), "l"(src) : "memory")
#define CP_COMMIT()  asm volatile("cp.async.commit_group;" ::: "memory")
#define CP_WAIT1()   asm volatile("cp.async.wait_group 1;" ::: "memory")
#define CP_WAIT0()   asm volatile("cp.async.wait_group 0;" ::: "memory")

#define LDMATRIX_X4(r, addr) \
    asm volatile("ldmatrix.sync.aligned.m8n8.x4.shared.b16 {%0,%1,%2,%3}, [%4];" \
        : "=r"((r)[0]), "=r"((r)[1]), "=r"((r)[2]), "=r"((r)[3]) : "r"(addr))

#define MMA16816(c, a, b0, b1) \
    asm volatile("mma.sync.aligned.m16n8k16.row.col.f32.bf16.bf16.f32 " \
        "{%0,%1,%2,%3},{%4,%5,%6,%7},{%8,%9},{%0,%1,%2,%3};" \
        : "+f"((c)[0]), "+f"((c)[1]), "+f"((c)[2]), "+f"((c)[3]) \
        : "r"((a)[0]), "r"((a)[1]), "r"((a)[2]), "r"((a)[3]), "r"(b0), "r"(b1))

// ---------------- multi-term bf16 NT GEMM: C = sum_t A_t @ B_t^T + bias ----
// A_t[M,K], B_t[N,K] bf16 (K-contig). M,N mult of 128, K mult of 32.
struct GemmA {
    const __nv_bfloat16* A[3];
    const __nv_bfloat16* B[3];
    const float* bias;
    float* C;
    int K, KC, NC, Nn;   // KC = K/32, NC = nterms*KC
};

__global__ __launch_bounds__(256, 1) void gemm_bf16(GemmA g)
{
    __shared__ __align__(16) unsigned char sm[2][20480];  // [stage][A:10240|B:10240], 80B row pitch
    const int tid = threadIdx.x, lane = tid & 31, wid = tid >> 5;
    const int wm = wid & 3, wn = wid >> 2;            // 4x2 warp grid, warp tile 32x64
    const int m0 = blockIdx.y * 128, n0 = blockIdx.x * 128;
    const uint32_t sb = smem_u32(sm);

    const int r0 = tid >> 2, u0 = tid & 3;            // loader: 2 x 16B per operand
    const int r1 = (tid + 256) >> 2, u1 = (tid + 256) & 3;

    float acc[2][8][4];
#pragma unroll
    for (int mf = 0; mf < 2; mf++)
#pragma unroll
        for (int nf = 0; nf < 8; nf++)
#pragma unroll
            for (int q = 0; q < 4; q++) acc[mf][nf][q] = 0.f;

#define ISSUE(c, st) do {                                                         \
        int _t = (c) / g.KC, _kc = (c) - _t * g.KC;                               \
        const __nv_bfloat16* _Ab = g.A[_t];                                       \
        const __nv_bfloat16* _Bb = g.B[_t];                                       \
        size_t _ka = (size_t)_kc * 32;                                            \
        uint32_t _dA = sb + (st) * 20480, _dB = _dA + 10240;                      \
        CP_ASYNC16(_dA + r0 * 80 + u0 * 16, _Ab + (size_t)(m0 + r0) * g.K + _ka + u0 * 8); \
        CP_ASYNC16(_dA + r1 * 80 + u1 * 16, _Ab + (size_t)(m0 + r1) * g.K + _ka + u1 * 8); \
        CP_ASYNC16(_dB + r0 * 80 + u0 * 16, _Bb + (size_t)(n0 + r0) * g.K + _ka + u0 * 8); \
        CP_ASYNC16(_dB + r1 * 80 + u1 * 16, _Bb + (size_t)(n0 + r1) * g.K + _ka + u1 * 8); \
    } while (0)

    ISSUE(0, 0);
    CP_COMMIT();

    for (int c = 0; c < g.NC; c++) {
        const int st = c & 1;
        if (c + 1 < g.NC) { ISSUE(c + 1, st ^ 1); CP_COMMIT(); CP_WAIT1(); }
        else              { CP_WAIT0(); }
        __syncthreads();

        const uint32_t aB = sb + st * 20480, bB = aB + 10240;
#pragma unroll
        for (int s = 0; s < 2; s++) {                 // two k16 steps per k32 chunk
            uint32_t a[2][4];
#pragma unroll
            for (int mf = 0; mf < 2; mf++) {
                uint32_t row  = wm * 32 + mf * 16 + (lane & 7) + ((lane >> 3) & 1) * 8;
                uint32_t unit = s * 2 + ((lane >> 4) & 1);
                LDMATRIX_X4(a[mf], aB + row * 80 + unit * 16);
            }
            uint32_t b[4][4];
#pragma unroll
            for (int jp = 0; jp < 4; jp++) {
                uint32_t row  = wn * 64 + jp * 16 + ((lane >> 4) & 1) * 8 + (lane & 7);
                uint32_t unit = s * 2 + ((lane >> 3) & 1);
                LDMATRIX_X4(b[jp], bB + row * 80 + unit * 16);
            }
#pragma unroll
            for (int mf = 0; mf < 2; mf++)
#pragma unroll
                for (int nf = 0; nf < 8; nf++)
                    MMA16816(acc[mf][nf], a[mf], b[nf >> 1][(nf & 1) * 2], b[nf >> 1][(nf & 1) * 2 + 1]);
        }
        __syncthreads();
    }
#undef ISSUE

    // epilogue: + bias, store fp32
    const int g4 = lane >> 2, t4 = lane & 3;
#pragma unroll
    for (int mf = 0; mf < 2; mf++) {
        const int row = m0 + wm * 32 + mf * 16 + g4;
#pragma unroll
        for (int nf = 0; nf < 8; nf++) {
            const int col = n0 + wn * 64 + nf * 8 + t4 * 2;
            float2 bb = *(const float2*)&g.bias[col];
            float2 v0 = make_float2(acc[mf][nf][0] + bb.x, acc[mf][nf][1] + bb.y);
            float2 v1 = make_float2(acc[mf][nf][2] + bb.x, acc[mf][nf][3] + bb.y);
            *(float2*)&g.C[(size_t)row * g.Nn + col]       = v0;
            *(float2*)&g.C[(size_t)(row + 8) * g.Nn + col] = v1;
        }
    }
}

// ---------------- fp32 -> 2x bf16 planes ------------------------------------
__global__ void split2(const float4* __restrict__ in, __nv_bfloat16* __restrict__ o0,
                       __nv_bfloat16* __restrict__ o1, int n4)
{
    int i = blockIdx.x * 256 + threadIdx.x;
    if (i >= n4) return;
    float4 x = in[i];
    float c[4] = {x.x, x.y, x.z, x.w};
    __align__(8) __nv_bfloat16 a0[4], a1[4];
#pragma unroll
    for (int k = 0; k < 4; k++) {
        __nv_bfloat16 b0 = __float2bfloat16(c[k]);
        a0[k] = b0;
        a1[k] = __float2bfloat16(c[k] - __bfloat162float(b0));
    }
    *(uint2*)(o0 + 4 * (size_t)i) = *(const uint2*)a0;
    *(uint2*)(o1 + 4 * (size_t)i) = *(const uint2*)a1;
}

// ---------------- LIF + risky detection -------------------------------------
// layer1: h fp32 -> s1 bf16, flag float4-groups within EPS of threshold
__global__ void lif_detect1(const float4* __restrict__ h, __nv_bfloat16* __restrict__ s1,
                            unsigned* __restrict__ list, unsigned* __restrict__ cnt, int plane4)
{
    int i = blockIdx.x * 256 + threadIdx.x;
    if (i >= plane4) return;
    float v[4] = {0.f, 0.f, 0.f, 0.f};
    bool risky = false;
#pragma unroll
    for (int t = 0; t < T_STEPS; t++) {
        float4 x = h[(size_t)t * plane4 + i];
        float c[4] = {x.x, x.y, x.z, x.w};
        __align__(8) __nv_bfloat16 sp[4];
#pragma unroll
        for (int j = 0; j < 4; j++) {
            float vn = v[j] + (c[j] - v[j]) * 0.5f;
            if (fabsf(vn - 1.0f) < EPS_) risky = true;
            if (vn >= 1.0f) { sp[j] = __float2bfloat16(1.0f); v[j] = 0.f; }
            else            { sp[j] = __float2bfloat16(0.0f); v[j] = vn; }
        }
        *(uint2*)(s1 + (size_t)t * plane4 * 4 + (size_t)i * 4) = *(const uint2*)sp;
    }
    if (risky) {
        unsigned p = atomicAdd(cnt, 1u);
        if (p < CAP_) list[p] = (unsigned)i;
    }
}

// layer2: y fp32 -> out fp32 spikes
__global__ void lif_detect2(const float4* __restrict__ y, float4* __restrict__ out,
                            unsigned* __restrict__ list, unsigned* __restrict__ cnt, int plane4)
{
    int i = blockIdx.x * 256 + threadIdx.x;
    if (i >= plane4) return;
    float v[4] = {0.f, 0.f, 0.f, 0.f};
    bool risky = false;
#pragma unroll
    for (int t = 0; t < T_STEPS; t++) {
        float4 x = y[(size_t)t * plane4 + i];
        float c[4] = {x.x, x.y, x.z, x.w};
        float4 sp;
        float* s = &sp.x;
#pragma unroll
        for (int j = 0; j < 4; j++) {
            float vn = v[j] + (c[j] - v[j]) * 0.5f;
            if (fabsf(vn - 1.0f) < EPS_) risky = true;
            if (vn >= 1.0f) { s[j] = 1.0f; v[j] = 0.f; }
            else            { s[j] = 0.0f; v[j] = vn; }
        }
        out[(size_t)t * plane4 + i] = sp;
    }
    if (risky) {
        unsigned p = atomicAdd(cnt, 1u);
        if (p < CAP_) list[p] = (unsigned)i;
    }
}

// ---------------- exact serial repairs (bitwise-match reference) -------------
__global__ void repair1(const float* __restrict__ x, const float* __restrict__ W1,
                        const float* __restrict__ b1, __nv_bfloat16* __restrict__ s1,
                        const unsigned* __restrict__ list, const unsigned* __restrict__ cnt)
{
    const size_t plane = (size_t)BN_ * H_;
    unsigned n = *cnt; if (n > CAP_) n = CAP_;
    for (unsigned idx = blockIdx.x * blockDim.x + threadIdx.x; idx < n * 4;
         idx += gridDim.x * blockDim.x) {
        unsigned p = list[idx >> 2] * 4u + (idx & 3u);   // neuron = bn*H + h
        int bn = (int)(p / H_), hc = (int)(p % H_);
        const float* w = W1 + (size_t)hc * D_;
        float v = 0.f;
#pragma unroll
        for (int t = 0; t < T_STEPS; t++) {
            const float* xr = x + (size_t)(t * BN_ + bn) * D_;
            float acc = 0.f;
            for (int k = 0; k < D_; k++) acc = fmaf(xr[k], w[k], acc);
            float hv = acc + b1[hc];
            float vn = v + (hv - v) * 0.5f;
            float sp;
            if (vn >= 1.0f) { sp = 1.0f; v = 0.f; } else { sp = 0.0f; v = vn; }
            s1[(size_t)t * plane + p] = __float2bfloat16(sp);
        }
    }
}

__global__ void repair2(const __nv_bfloat16* __restrict__ s1, const float* __restrict__ W2,
                        const float* __restrict__ b2, float* __restrict__ out,
                        const unsigned* __restrict__ list, const unsigned* __restrict__ cnt)
{
    const size_t plane = (size_t)BN_ * D_;
    unsigned n = *cnt; if (n > CAP_) n = CAP_;
    for (unsigned idx = blockIdx.x * blockDim.x + threadIdx.x; idx < n * 4;
         idx += gridDim.x * blockDim.x) {
        unsigned p = list[idx >> 2] * 4u + (idx & 3u);   // = bn*D + d
        int bn = (int)(p / D_), dc = (int)(p % D_);
        const float* w = W2 + (size_t)dc * H_;
        float v = 0.f;
#pragma unroll
        for (int t = 0; t < T_STEPS; t++) {
            const __nv_bfloat16* sr = s1 + (size_t)(t * BN_ + bn) * H_;
            float acc = 0.f;
            for (int k = 0; k < H_; k++) acc = fmaf(__bfloat162float(sr[k]), w[k], acc);
            float yv = acc + b2[dc];
            float vn = v + (yv - v) * 0.5f;
            float sp;
            if (vn >= 1.0f) { sp = 1.0f; v = 0.f; } else { sp = 0.0f; v = vn; }
            out[(size_t)t * plane + p] = sp;
        }
    }
}

// ---------------------------------------------------------------------------
extern "C" void kernel_launch(void* const* d_in, const int* in_sizes, int n_in,
                              void* d_out, int out_size)
{
    const float* x  = (const float*)d_in[0];
    const float* W1 = (const float*)d_in[1];
    const float* b1 = (const float*)d_in[2];
    const float* W2 = (const float*)d_in[3];
    const float* b2 = (const float*)d_in[4];
    float* out = (float*)d_out;

    __nv_bfloat16 *x0, *x1, *w1p, *w2p, *s1;
    float *hf, *yf;
    unsigned *cnt, *l1, *l2;
    cudaGetSymbolAddress((void**)&x0, g_x0);
    cudaGetSymbolAddress((void**)&x1, g_x1);
    cudaGetSymbolAddress((void**)&w1p, g_w1p);
    cudaGetSymbolAddress((void**)&w2p, g_w2p);
    cudaGetSymbolAddress((void**)&hf, g_hf);
    cudaGetSymbolAddress((void**)&yf, g_yf);
    cudaGetSymbolAddress((void**)&s1, g_s1);
    cudaGetSymbolAddress((void**)&cnt, g_cnt);
    cudaGetSymbolAddress((void**)&l1, g_list1);
    cudaGetSymbolAddress((void**)&l2, g_list2);

    cudaMemsetAsync(cnt, 0, 2 * sizeof(unsigned));

    // plane splits
    { int n4 = (int)((size_t)ROWS_ * D_ / 4);
      split2<<<(n4 + 255) / 256, 256>>>((const float4*)x, x0, x1, n4); }
    { int n4 = (int)((size_t)H_ * D_ / 4);
      split2<<<(n4 + 255) / 256, 256>>>((const float4*)W1, w1p, w1p + (size_t)H_ * D_, n4);
      split2<<<(n4 + 255) / 256, 256>>>((const float4*)W2, w2p, w2p + (size_t)D_ * H_, n4); }

    // fc1 predictor: x0*w0 + x0*w1 + x1*w0
    {
        GemmA a;
        a.A[0] = x0; a.A[1] = x0; a.A[2] = x1;
        a.B[0] = w1p; a.B[1] = w1p + (size_t)H_ * D_; a.B[2] = w1p;
        a.bias = b1; a.C = hf; a.K = D_; a.KC = D_ / 32; a.NC = 3 * (D_ / 32); a.Nn = H_;
        gemm_bf16<<<dim3(H_ / 128, ROWS_ / 128), 256>>>(a);
    }
    // LIF1 + detect + exact repair
    {
        int plane4 = BN_ * H_ / 4;
        lif_detect1<<<(plane4 + 255) / 256, 256>>>((const float4*)hf, s1, l1, cnt, plane4);
        repair1<<<256, 256>>>(x, W1, b1, s1, l1, cnt);
    }
    // fc2 predictor: s1*w20 + s1*w21 (spikes exact in bf16)
    {
        GemmA a;
        a.A[0] = s1; a.A[1] = s1; a.A[2] = s1;
        a.B[0] = w2p; a.B[1] = w2p + (size_t)D_ * H_; a.B[2] = w2p;
        a.bias = b2; a.C = yf; a.K = H_; a.KC = H_ / 32; a.NC = 2 * (H_ / 32); a.Nn = D_;
        gemm_bf16<<<dim3(D_ / 128, ROWS_ / 128), 256>>>(a);
    }
    // LIF2 + detect + exact repair
    {
        int plane4 = BN_ * D_ / 4;
        lif_detect2<<<(plane4 + 255) / 256, 256>>>((const float4*)yf, (float4*)out, l2, cnt + 1, plane4);
        repair2<<<256, 256>>>(s1, W2, b2, out, l2, cnt + 1);
    }
}

// round 9
// speedup vs baseline: 1.4721x; 1.3003x over previous
#include <cuda_runtime.h>
#include <cuda_bf16.h>
#include <cstdint>

#define T_STEPS 4
#define BN_     6272
#define ROWS_   25088
#define D_      768
#define H_      3072
#define EPS_    1e-3f
#define CAP_    (1u << 20)
#define STAGES  4
#define STG_B   20480          /* per-stage: A 128x80 + B 128x80 */
#define SMEM_SZ (STAGES * STG_B)

// ---------------- scratch (static device globals; no allocations) ----------
__device__ __nv_bfloat16 g_x0[(size_t)ROWS_ * D_];
__device__ __nv_bfloat16 g_x1[(size_t)ROWS_ * D_];
__device__ __nv_bfloat16 g_w1p[2][(size_t)H_ * D_];
__device__ __nv_bfloat16 g_w2p[2][(size_t)D_ * H_];
__device__ float         g_hf[(size_t)ROWS_ * H_];
__device__ __nv_bfloat16 g_s1[(size_t)ROWS_ * H_];
__device__ float         g_yf[(size_t)ROWS_ * D_];
__device__ unsigned      g_cnt[2];
__device__ unsigned      g_list1[CAP_];
__device__ unsigned      g_list2[CAP_];

// ---------------- PTX helpers (sm_80-class; compile under sm_103) ----------
__device__ __forceinline__ uint32_t smem_u32(const void* p) {
    uint32_t a;
    asm("{ .reg .u64 t; cvta.to.shared.u64 t, %1; cvt.u32.u64 %0, t; }"
        : "=r"(a) : "l"(p));
    return a;
}
#define CP_ASYNC16(dst, src) \
    asm volatile("cp.async.ca.shared.global [%0], [%1], 16;" :: "r"(dst), "l"(src) : "memory")
#define CP_COMMIT()  asm volatile("cp.async.commit_group;" ::: "memory")
#define CP_WAIT2()   asm volatile("cp.async.wait_group 2;" ::: "memory")
#define CP_WAIT0()   asm volatile("cp.async.wait_group 0;" ::: "memory")

#define LDMATRIX_X4(r, addr) \
    asm volatile("ldmatrix.sync.aligned.m8n8.x4.shared.b16 {%0,%1,%2,%3}, [%4];" \
        : "=r"((r)[0]), "=r"((r)[1]), "=r"((r)[2]), "=r"((r)[3]) : "r"(addr))

#define MMA16816(c, a, b0, b1) \
    asm volatile("mma.sync.aligned.m16n8k16.row.col.f32.bf16.bf16.f32 " \
        "{%0,%1,%2,%3},{%4,%5,%6,%7},{%8,%9},{%0,%1,%2,%3};" \
        : "+f"((c)[0]), "+f"((c)[1]), "+f"((c)[2]), "+f"((c)[3]) \
        : "r"((a)[0]), "r"((a)[1]), "r"((a)[2]), "r"((a)[3]), "r"(b0), "r"(b1))

// ---------------- multi-term bf16 NT GEMM: C = sum_t A_t @ B_t^T + bias ----
struct GemmA {
    const __nv_bfloat16* A[3];
    const __nv_bfloat16* B[3];
    const float* bias;
    float* C;
    int K, KC, NC, Nn;   // KC = K/32, NC = nterms*KC
};

__global__ __launch_bounds__(256, 2) void gemm_bf16(GemmA g)
{
    extern __shared__ __align__(16) unsigned char smd[];
    const int tid = threadIdx.x, lane = tid & 31, wid = tid >> 5;
    const int wm = wid & 3, wn = wid >> 2;            // 4x2 warp grid, warp tile 32x64
    const int m0 = blockIdx.y * 128, n0 = blockIdx.x * 128;
    const uint32_t sb = smem_u32(smd);

    const int r0 = tid >> 2, u0 = tid & 3;
    const int r1 = r0 + 64,  u1 = u0;

    float acc[2][8][4];
#pragma unroll
    for (int mf = 0; mf < 2; mf++)
#pragma unroll
        for (int nf = 0; nf < 8; nf++)
#pragma unroll
            for (int q = 0; q < 4; q++) acc[mf][nf][q] = 0.f;

#define ISSUE(c, st) do {                                                         \
        int _t = (c) / g.KC, _kc = (c) - _t * g.KC;                               \
        const __nv_bfloat16* _Ab = g.A[_t];                                       \
        const __nv_bfloat16* _Bb = g.B[_t];                                       \
        size_t _ka = (size_t)_kc * 32;                                            \
        uint32_t _dA = sb + (st) * STG_B, _dB = _dA + 10240;                      \
        CP_ASYNC16(_dA + r0 * 80 + u0 * 16, _Ab + (size_t)(m0 + r0) * g.K + _ka + u0 * 8); \
        CP_ASYNC16(_dA + r1 * 80 + u1 * 16, _Ab + (size_t)(m0 + r1) * g.K + _ka + u1 * 8); \
        CP_ASYNC16(_dB + r0 * 80 + u0 * 16, _Bb + (size_t)(n0 + r0) * g.K + _ka + u0 * 8); \
        CP_ASYNC16(_dB + r1 * 80 + u1 * 16, _Bb + (size_t)(n0 + r1) * g.K + _ka + u1 * 8); \
    } while (0)

    // prologue: fill 3 stages
#pragma unroll
    for (int s = 0; s < STAGES - 1; s++) {
        if (s < g.NC) ISSUE(s, s);
        CP_COMMIT();
    }

    for (int c = 0; c < g.NC; c++) {
        const int st = c & (STAGES - 1);
        CP_WAIT2();                       // stage c resident
        __syncthreads();                  // all readers of stage (c-1) done
        {
            const int nx = c + STAGES - 1;
            if (nx < g.NC) ISSUE(nx, nx & (STAGES - 1));
            CP_COMMIT();
        }

        const uint32_t aB = sb + st * STG_B, bB = aB + 10240;
#pragma unroll
        for (int s = 0; s < 2; s++) {     // two k16 steps per k32 chunk
            uint32_t a[2][4];
#pragma unroll
            for (int mf = 0; mf < 2; mf++) {
                uint32_t row  = wm * 32 + mf * 16 + (lane & 7) + ((lane >> 3) & 1) * 8;
                uint32_t unit = s * 2 + ((lane >> 4) & 1);
                LDMATRIX_X4(a[mf], aB + row * 80 + unit * 16);
            }
            uint32_t b[4][4];
#pragma unroll
            for (int jp = 0; jp < 4; jp++) {
                uint32_t row  = wn * 64 + jp * 16 + ((lane >> 4) & 1) * 8 + (lane & 7);
                uint32_t unit = s * 2 + ((lane >> 3) & 1);
                LDMATRIX_X4(b[jp], bB + row * 80 + unit * 16);
            }
#pragma unroll
            for (int mf = 0; mf < 2; mf++)
#pragma unroll
                for (int nf = 0; nf < 8; nf++)
                    MMA16816(acc[mf][nf], a[mf], b[nf >> 1][(nf & 1) * 2], b[nf >> 1][(nf & 1) * 2 + 1]);
        }
    }
#undef ISSUE
    CP_WAIT0();

    // epilogue: + bias, store fp32
    const int g4 = lane >> 2, t4 = lane & 3;
#pragma unroll
    for (int mf = 0; mf < 2; mf++) {
        const int row = m0 + wm * 32 + mf * 16 + g4;
#pragma unroll
        for (int nf = 0; nf < 8; nf++) {
            const int col = n0 + wn * 64 + nf * 8 + t4 * 2;
            float2 bb = *(const float2*)&g.bias[col];
            float2 v0 = make_float2(acc[mf][nf][0] + bb.x, acc[mf][nf][1] + bb.y);
            float2 v1 = make_float2(acc[mf][nf][2] + bb.x, acc[mf][nf][3] + bb.y);
            *(float2*)&g.C[(size_t)row * g.Nn + col]       = v0;
            *(float2*)&g.C[(size_t)(row + 8) * g.Nn + col] = v1;
        }
    }
}

// ---------------- fp32 -> 2x bf16 planes ------------------------------------
__global__ void split2(const float4* __restrict__ in, __nv_bfloat16* __restrict__ o0,
                       __nv_bfloat16* __restrict__ o1, int n4)
{
    int i = blockIdx.x * 256 + threadIdx.x;
    if (i >= n4) return;
    float4 x = in[i];
    float c[4] = {x.x, x.y, x.z, x.w};
    __align__(8) __nv_bfloat16 a0[4], a1[4];
#pragma unroll
    for (int k = 0; k < 4; k++) {
        __nv_bfloat16 b0 = __float2bfloat16(c[k]);
        a0[k] = b0;
        a1[k] = __float2bfloat16(c[k] - __bfloat162float(b0));
    }
    *(uint2*)(o0 + 4 * (size_t)i) = *(const uint2*)a0;
    *(uint2*)(o1 + 4 * (size_t)i) = *(const uint2*)a1;
}

// ---------------- LIF + risky detection -------------------------------------
__global__ void lif_detect1(const float4* __restrict__ h, __nv_bfloat16* __restrict__ s1,
                            unsigned* __restrict__ list, unsigned* __restrict__ cnt, int plane4)
{
    int i = blockIdx.x * 256 + threadIdx.x;
    if (i >= plane4) return;
    float v[4] = {0.f, 0.f, 0.f, 0.f};
    bool risky = false;
#pragma unroll
    for (int t = 0; t < T_STEPS; t++) {
        float4 x = h[(size_t)t * plane4 + i];
        float c[4] = {x.x, x.y, x.z, x.w};
        __align__(8) __nv_bfloat16 sp[4];
#pragma unroll
        for (int j = 0; j < 4; j++) {
            float vn = v[j] + (c[j] - v[j]) * 0.5f;
            if (fabsf(vn - 1.0f) < EPS_) risky = true;
            if (vn >= 1.0f) { sp[j] = __float2bfloat16(1.0f); v[j] = 0.f; }
            else            { sp[j] = __float2bfloat16(0.0f); v[j] = vn; }
        }
        *(uint2*)(s1 + (size_t)t * plane4 * 4 + (size_t)i * 4) = *(const uint2*)sp;
    }
    if (risky) {
        unsigned p = atomicAdd(cnt, 1u);
        if (p < CAP_) list[p] = (unsigned)i;
    }
}

__global__ void lif_detect2(const float4* __restrict__ y, float4* __restrict__ out,
                            unsigned* __restrict__ list, unsigned* __restrict__ cnt, int plane4)
{
    int i = blockIdx.x * 256 + threadIdx.x;
    if (i >= plane4) return;
    float v[4] = {0.f, 0.f, 0.f, 0.f};
    bool risky = false;
#pragma unroll
    for (int t = 0; t < T_STEPS; t++) {
        float4 x = y[(size_t)t * plane4 + i];
        float c[4] = {x.x, x.y, x.z, x.w};
        float4 sp;
        float* s = &sp.x;
#pragma unroll
        for (int j = 0; j < 4; j++) {
            float vn = v[j] + (c[j] - v[j]) * 0.5f;
            if (fabsf(vn - 1.0f) < EPS_) risky = true;
            if (vn >= 1.0f) { s[j] = 1.0f; v[j] = 0.f; }
            else            { s[j] = 0.0f; v[j] = vn; }
        }
        out[(size_t)t * plane4 + i] = sp;
    }
    if (risky) {
        unsigned p = atomicAdd(cnt, 1u);
        if (p < CAP_) list[p] = (unsigned)i;
    }
}

// ---------------- exact serial repairs (bitwise-match reference) -------------
__global__ void repair1(const float* __restrict__ x, const float* __restrict__ W1,
                        const float* __restrict__ b1, __nv_bfloat16* __restrict__ s1,
                        const unsigned* __restrict__ list, const unsigned* __restrict__ cnt)
{
    const size_t plane = (size_t)BN_ * H_;
    unsigned n = *cnt; if (n > CAP_) n = CAP_;
    for (unsigned idx = blockIdx.x * blockDim.x + threadIdx.x; idx < n * 4;
         idx += gridDim.x * blockDim.x) {
        unsigned p = list[idx >> 2] * 4u + (idx & 3u);
        int bn = (int)(p / H_), hc = (int)(p % H_);
        const float* w = W1 + (size_t)hc * D_;
        float v = 0.f;
#pragma unroll
        for (int t = 0; t < T_STEPS; t++) {
            const float* xr = x + (size_t)(t * BN_ + bn) * D_;
            float acc = 0.f;
            for (int k = 0; k < D_; k++) acc = fmaf(xr[k], w[k], acc);
            float hv = acc + b1[hc];
            float vn = v + (hv - v) * 0.5f;
            float sp;
            if (vn >= 1.0f) { sp = 1.0f; v = 0.f; } else { sp = 0.0f; v = vn; }
            s1[(size_t)t * plane + p] = __float2bfloat16(sp);
        }
    }
}

__global__ void repair2(const __nv_bfloat16* __restrict__ s1, const float* __restrict__ W2,
                        const float* __restrict__ b2, float* __restrict__ out,
                        const unsigned* __restrict__ list, const unsigned* __restrict__ cnt)
{
    const size_t plane = (size_t)BN_ * D_;
    unsigned n = *cnt; if (n > CAP_) n = CAP_;
    for (unsigned idx = blockIdx.x * blockDim.x + threadIdx.x; idx < n * 4;
         idx += gridDim.x * blockDim.x) {
        unsigned p = list[idx >> 2] * 4u + (idx & 3u);
        int bn = (int)(p / D_), dc = (int)(p % D_);
        const float* w = W2 + (size_t)dc * H_;
        float v = 0.f;
#pragma unroll
        for (int t = 0; t < T_STEPS; t++) {
            const __nv_bfloat16* sr = s1 + (size_t)(t * BN_ + bn) * H_;
            float acc = 0.f;
            for (int k = 0; k < H_; k++) acc = fmaf(__bfloat162float(sr[k]), w[k], acc);
            float yv = acc + b2[dc];
            float vn = v + (yv - v) * 0.5f;
            float sp;
            if (vn >= 1.0f) { sp = 1.0f; v = 0.f; } else { sp = 0.0f; v = vn; }
            out[(size_t)t * plane + p] = sp;
        }
    }
}

// ---------------------------------------------------------------------------
extern "C" void kernel_launch(void* const* d_in, const int* in_sizes, int n_in,
                              void* d_out, int out_size)
{
    const float* x  = (const float*)d_in[0];
    const float* W1 = (const float*)d_in[1];
    const float* b1 = (const float*)d_in[2];
    const float* W2 = (const float*)d_in[3];
    const float* b2 = (const float*)d_in[4];
    float* out = (float*)d_out;

    __nv_bfloat16 *x0, *x1, *w1p, *w2p, *s1;
    float *hf, *yf;
    unsigned *cnt, *l1, *l2;
    cudaGetSymbolAddress((void**)&x0, g_x0);
    cudaGetSymbolAddress((void**)&x1, g_x1);
    cudaGetSymbolAddress((void**)&w1p, g_w1p);
    cudaGetSymbolAddress((void**)&w2p, g_w2p);
    cudaGetSymbolAddress((void**)&hf, g_hf);
    cudaGetSymbolAddress((void**)&yf, g_yf);
    cudaGetSymbolAddress((void**)&s1, g_s1);
    cudaGetSymbolAddress((void**)&cnt, g_cnt);
    cudaGetSymbolAddress((void**)&l1, g_list1);
    cudaGetSymbolAddress((void**)&l2, g_list2);

    cudaFuncSetAttribute(gemm_bf16, cudaFuncAttributeMaxDynamicSharedMemorySize, SMEM_SZ);
    cudaMemsetAsync(cnt, 0, 2 * sizeof(unsigned));

    // plane splits
    { int n4 = (int)((size_t)ROWS_ * D_ / 4);
      split2<<<(n4 + 255) / 256, 256>>>((const float4*)x, x0, x1, n4); }
    { int n4 = (int)((size_t)H_ * D_ / 4);
      split2<<<(n4 + 255) / 256, 256>>>((const float4*)W1, w1p, w1p + (size_t)H_ * D_, n4);
      split2<<<(n4 + 255) / 256, 256>>>((const float4*)W2, w2p, w2p + (size_t)D_ * H_, n4); }

    // fc1 predictor: x0*w0 + x0*w1 + x1*w0
    {
        GemmA a;
        a.A[0] = x0; a.A[1] = x0; a.A[2] = x1;
        a.B[0] = w1p; a.B[1] = w1p + (size_t)H_ * D_; a.B[2] = w1p;
        a.bias = b1; a.C = hf; a.K = D_; a.KC = D_ / 32; a.NC = 3 * (D_ / 32); a.Nn = H_;
        gemm_bf16<<<dim3(H_ / 128, ROWS_ / 128), 256, SMEM_SZ>>>(a);
    }
    // LIF1 + detect + exact repair
    {
        int plane4 = BN_ * H_ / 4;
        lif_detect1<<<(plane4 + 255) / 256, 256>>>((const float4*)hf, s1, l1, cnt, plane4);
        repair1<<<256, 256>>>(x, W1, b1, s1, l1, cnt);
    }
    // fc2 predictor: s1*w20 + s1*w21 (spikes exact in bf16)
    {
        GemmA a;
        a.A[0] = s1; a.A[1] = s1; a.A[2] = s1;
        a.B[0] = w2p; a.B[1] = w2p + (size_t)D_ * H_; a.B[2] = w2p;
        a.bias = b2; a.C = yf; a.K = H_; a.KC = H_ / 32; a.NC = 2 * (H_ / 32); a.Nn = D_;
        gemm_bf16<<<dim3(D_ / 128, ROWS_ / 128), 256, SMEM_SZ>>>(a);
    }
    // LIF2 + detect + exact repair
    {
        int plane4 = BN_ * D_ / 4;
        lif_detect2<<<(plane4 + 255) / 256, 256>>>((const float4*)yf, (float4*)out, l2, cnt + 1, plane4);
        repair2<<<256, 256>>>(s1, W2, b2, out, l2, cnt + 1);
    }
}

// round 12
// speedup vs baseline: 3.3482x; 2.2745x over previous
#include <cuda_runtime.h>
#include <cuda_fp16.h>
#include <cstdint>

#define T_STEPS 4
#define BN_     6272
#define ROWS_   25088
#define D_      768
#define H_      3072
#define EPS1_   2e-3f
#define EPS2_   1.5e-3f
#define CAP_    (1u << 20)
#define STAGES  4
#define STG_B   20480          /* per-stage: A 128x(32+8pad) + B same, 80B pitch */
#define SMEM_SZ (STAGES * STG_B)

// ---------------- scratch (static device globals; no allocations) ----------
__device__ __half  g_xh[(size_t)ROWS_ * D_];
__device__ __half  g_w1h[(size_t)H_ * D_];
__device__ __half  g_w2h[(size_t)D_ * H_];
__device__ float   g_hf[(size_t)ROWS_ * H_];
__device__ __half  g_s1[(size_t)ROWS_ * H_];     // spikes: exact 0/1 in fp16
__device__ float   g_yf[(size_t)ROWS_ * D_];
__device__ unsigned g_cnt[2];
__device__ unsigned g_list1[CAP_];
__device__ unsigned g_list2[CAP_];

// ---------------- PTX helpers (sm_80-class; compile under sm_103) ----------
__device__ __forceinline__ uint32_t smem_u32(const void* p) {
    uint32_t a;
    asm("{ .reg .u64 t; cvta.to.shared.u64 t, %1; cvt.u32.u64 %0, t; }"
        : "=r"(a) : "l"(p));
    return a;
}
#define CP_ASYNC16(dst, src) \
    asm volatile("cp.async.ca.shared.global [%0], [%1], 16;" :: "r"(dst), "l"(src) : "memory")
#define CP_COMMIT()  asm volatile("cp.async.commit_group;" ::: "memory")
#define CP_WAIT2()   asm volatile("cp.async.wait_group 2;" ::: "memory")
#define CP_WAIT0()   asm volatile("cp.async.wait_group 0;" ::: "memory")

#define LDMATRIX_X4(r, addr) \
    asm volatile("ldmatrix.sync.aligned.m8n8.x4.shared.b16 {%0,%1,%2,%3}, [%4];" \
        : "=r"((r)[0]), "=r"((r)[1]), "=r"((r)[2]), "=r"((r)[3]) : "r"(addr))

#define MMA16816(c, a, b0, b1) \
    asm volatile("mma.sync.aligned.m16n8k16.row.col.f32.f16.f16.f32 " \
        "{%0,%1,%2,%3},{%4,%5,%6,%7},{%8,%9},{%0,%1,%2,%3};" \
        : "+f"((c)[0]), "+f"((c)[1]), "+f"((c)[2]), "+f"((c)[3]) \
        : "r"((a)[0]), "r"((a)[1]), "r"((a)[2]), "r"((a)[3]), "r"(b0), "r"(b1))

// ---------------- single fp16 NT GEMM: C[M,N] = A @ B^T + bias -------------
struct GemmA {
    const __half* A;
    const __half* B;
    const float* bias;
    float* C;
    int K, NC, Nn;   // NC = K/32
};

__global__ __launch_bounds__(256, 2) void gemm_fp16(GemmA g)
{
    extern __shared__ __align__(16) unsigned char smd[];
    const int tid = threadIdx.x, lane = tid & 31, wid = tid >> 5;
    const int wm = wid & 3, wn = wid >> 2;            // 4x2 warp grid, warp tile 32x64
    const int m0 = blockIdx.y * 128, n0 = blockIdx.x * 128;
    const uint32_t sb = smem_u32(smd);

    const int r0 = tid >> 2, u0 = tid & 3;
    const int r1 = r0 + 64,  u1 = u0;

    float acc[2][8][4];
#pragma unroll
    for (int mf = 0; mf < 2; mf++)
#pragma unroll
        for (int nf = 0; nf < 8; nf++)
#pragma unroll
            for (int q = 0; q < 4; q++) acc[mf][nf][q] = 0.f;

#define ISSUE(c, st) do {                                                         \
        size_t _ka = (size_t)(c) * 32;                                            \
        uint32_t _dA = sb + (st) * STG_B, _dB = _dA + 10240;                      \
        CP_ASYNC16(_dA + r0 * 80 + u0 * 16, g.A + (size_t)(m0 + r0) * g.K + _ka + u0 * 8); \
        CP_ASYNC16(_dA + r1 * 80 + u1 * 16, g.A + (size_t)(m0 + r1) * g.K + _ka + u1 * 8); \
        CP_ASYNC16(_dB + r0 * 80 + u0 * 16, g.B + (size_t)(n0 + r0) * g.K + _ka + u0 * 8); \
        CP_ASYNC16(_dB + r1 * 80 + u1 * 16, g.B + (size_t)(n0 + r1) * g.K + _ka + u1 * 8); \
    } while (0)

    // prologue: fill 3 stages
#pragma unroll
    for (int s = 0; s < STAGES - 1; s++) {
        if (s < g.NC) ISSUE(s, s);
        CP_COMMIT();
    }

    for (int c = 0; c < g.NC; c++) {
        const int st = c & (STAGES - 1);
        CP_WAIT2();                       // stage c resident
        __syncthreads();                  // readers of stage (c-1) done
        {
            const int nx = c + STAGES - 1;
            if (nx < g.NC) ISSUE(nx, nx & (STAGES - 1));
            CP_COMMIT();
        }

        const uint32_t aB = sb + st * STG_B, bB = aB + 10240;
#pragma unroll
        for (int s = 0; s < 2; s++) {     // two k16 steps per k32 chunk
            uint32_t a[2][4];
#pragma unroll
            for (int mf = 0; mf < 2; mf++) {
                uint32_t row  = wm * 32 + mf * 16 + (lane & 7) + ((lane >> 3) & 1) * 8;
                uint32_t unit = s * 2 + ((lane >> 4) & 1);
                LDMATRIX_X4(a[mf], aB + row * 80 + unit * 16);
            }
            uint32_t b[4][4];
#pragma unroll
            for (int jp = 0; jp < 4; jp++) {
                uint32_t row  = wn * 64 + jp * 16 + ((lane >> 4) & 1) * 8 + (lane & 7);
                uint32_t unit = s * 2 + ((lane >> 3) & 1);
                LDMATRIX_X4(b[jp], bB + row * 80 + unit * 16);
            }
#pragma unroll
            for (int mf = 0; mf < 2; mf++)
#pragma unroll
                for (int nf = 0; nf < 8; nf++)
                    MMA16816(acc[mf][nf], a[mf], b[nf >> 1][(nf & 1) * 2], b[nf >> 1][(nf & 1) * 2 + 1]);
        }
    }
#undef ISSUE
    CP_WAIT0();

    // epilogue: + bias, store fp32
    const int g4 = lane >> 2, t4 = lane & 3;
#pragma unroll
    for (int mf = 0; mf < 2; mf++) {
        const int row = m0 + wm * 32 + mf * 16 + g4;
#pragma unroll
        for (int nf = 0; nf < 8; nf++) {
            const int col = n0 + wn * 64 + nf * 8 + t4 * 2;
            float2 bb = *(const float2*)&g.bias[col];
            float2 v0 = make_float2(acc[mf][nf][0] + bb.x, acc[mf][nf][1] + bb.y);
            float2 v1 = make_float2(acc[mf][nf][2] + bb.x, acc[mf][nf][3] + bb.y);
            *(float2*)&g.C[(size_t)row * g.Nn + col]       = v0;
            *(float2*)&g.C[(size_t)(row + 8) * g.Nn + col] = v1;
        }
    }
}

// ---------------- fp32 -> fp16 cast -----------------------------------------
__global__ void cast_h(const float4* __restrict__ in, __half* __restrict__ o, int n4)
{
    int i = blockIdx.x * 256 + threadIdx.x;
    if (i >= n4) return;
    float4 x = in[i];
    __align__(8) __half h[4] = {__float2half(x.x), __float2half(x.y),
                                __float2half(x.z), __float2half(x.w)};
    *(uint2*)(o + 4 * (size_t)i) = *(const uint2*)h;
}

// ---------------- LIF + risky detection -------------------------------------
__global__ void lif_detect1(const float4* __restrict__ h, __half* __restrict__ s1,
                            unsigned* __restrict__ list, unsigned* __restrict__ cnt, int plane4)
{
    int i = blockIdx.x * 256 + threadIdx.x;
    if (i >= plane4) return;
    float v[4] = {0.f, 0.f, 0.f, 0.f};
    bool risky = false;
#pragma unroll
    for (int t = 0; t < T_STEPS; t++) {
        float4 x = h[(size_t)t * plane4 + i];
        float c[4] = {x.x, x.y, x.z, x.w};
        __align__(8) __half sp[4];
#pragma unroll
        for (int j = 0; j < 4; j++) {
            float vn = v[j] + (c[j] - v[j]) * 0.5f;
            if (fabsf(vn - 1.0f) < EPS1_) risky = true;
            if (vn >= 1.0f) { sp[j] = __float2half(1.0f); v[j] = 0.f; }
            else            { sp[j] = __float2half(0.0f); v[j] = vn; }
        }
        *(uint2*)(s1 + (size_t)t * plane4 * 4 + (size_t)i * 4) = *(const uint2*)sp;
    }
    if (risky) {
        unsigned p = atomicAdd(cnt, 1u);
        if (p < CAP_) list[p] = (unsigned)i;
    }
}

__global__ void lif_detect2(const float4* __restrict__ y, float4* __restrict__ out,
                            unsigned* __restrict__ list, unsigned* __restrict__ cnt, int plane4)
{
    int i = blockIdx.x * 256 + threadIdx.x;
    if (i >= plane4) return;
    float v[4] = {0.f, 0.f, 0.f, 0.f};
    bool risky = false;
#pragma unroll
    for (int t = 0; t < T_STEPS; t++) {
        float4 x = y[(size_t)t * plane4 + i];
        float c[4] = {x.x, x.y, x.z, x.w};
        float4 sp;
        float* s = &sp.x;
#pragma unroll
        for (int j = 0; j < 4; j++) {
            float vn = v[j] + (c[j] - v[j]) * 0.5f;
            if (fabsf(vn - 1.0f) < EPS2_) risky = true;
            if (vn >= 1.0f) { s[j] = 1.0f; v[j] = 0.f; }
            else            { s[j] = 0.0f; v[j] = vn; }
        }
        out[(size_t)t * plane4 + i] = sp;
    }
    if (risky) {
        unsigned p = atomicAdd(cnt, 1u);
        if (p < CAP_) list[p] = (unsigned)i;
    }
}

// ---------------- exact serial repairs (k-ascending fp32, float4 loads) -----
__global__ void repair1(const float* __restrict__ x, const float* __restrict__ W1,
                        const float* __restrict__ b1, __half* __restrict__ s1,
                        const unsigned* __restrict__ list, const unsigned* __restrict__ cnt)
{
    const size_t plane = (size_t)BN_ * H_;
    unsigned n = *cnt; if (n > CAP_) n = CAP_;
    for (unsigned idx = blockIdx.x * blockDim.x + threadIdx.x; idx < n * 4;
         idx += gridDim.x * blockDim.x) {
        unsigned p = list[idx >> 2] * 4u + (idx & 3u);
        int bn = (int)(p / H_), hc = (int)(p % H_);
        const float4* w = (const float4*)(W1 + (size_t)hc * D_);
        float v = 0.f;
#pragma unroll
        for (int t = 0; t < T_STEPS; t++) {
            const float4* xr = (const float4*)(x + (size_t)(t * BN_ + bn) * D_);
            float acc = 0.f;
            for (int q = 0; q < D_ / 4; q++) {        // serial, k-ascending
                float4 xv = xr[q], wv = w[q];
                acc = fmaf(xv.x, wv.x, acc);
                acc = fmaf(xv.y, wv.y, acc);
                acc = fmaf(xv.z, wv.z, acc);
                acc = fmaf(xv.w, wv.w, acc);
            }
            float hv = acc + b1[hc];
            float vn = v + (hv - v) * 0.5f;
            float sp;
            if (vn >= 1.0f) { sp = 1.0f; v = 0.f; } else { sp = 0.0f; v = vn; }
            s1[(size_t)t * plane + p] = __float2half(sp);
        }
    }
}

__global__ void repair2(const __half* __restrict__ s1, const float* __restrict__ W2,
                        const float* __restrict__ b2, float* __restrict__ out,
                        const unsigned* __restrict__ list, const unsigned* __restrict__ cnt)
{
    const size_t plane = (size_t)BN_ * D_;
    unsigned n = *cnt; if (n > CAP_) n = CAP_;
    for (unsigned idx = blockIdx.x * blockDim.x + threadIdx.x; idx < n * 4;
         idx += gridDim.x * blockDim.x) {
        unsigned p = list[idx >> 2] * 4u + (idx & 3u);
        int bn = (int)(p / D_), dc = (int)(p % D_);
        const float4* w = (const float4*)(W2 + (size_t)dc * H_);
        float v = 0.f;
#pragma unroll
        for (int t = 0; t < T_STEPS; t++) {
            const __half2* sr = (const __half2*)(s1 + (size_t)(t * BN_ + bn) * H_);
            float acc = 0.f;
            for (int q = 0; q < H_ / 4; q++) {        // serial, k-ascending
                __half2 s01 = sr[2 * q], s23 = sr[2 * q + 1];
                float4 wv = w[q];
                acc = fmaf(__low2float(s01),  wv.x, acc);
                acc = fmaf(__high2float(s01), wv.y, acc);
                acc = fmaf(__low2float(s23),  wv.z, acc);
                acc = fmaf(__high2float(s23), wv.w, acc);
            }
            float yv = acc + b2[dc];
            float vn = v + (yv - v) * 0.5f;
            float sp;
            if (vn >= 1.0f) { sp = 1.0f; v = 0.f; } else { sp = 0.0f; v = vn; }
            out[(size_t)t * plane + p] = sp;
        }
    }
}

// ---------------------------------------------------------------------------
extern "C" void kernel_launch(void* const* d_in, const int* in_sizes, int n_in,
                              void* d_out, int out_size)
{
    const float* x  = (const float*)d_in[0];
    const float* W1 = (const float*)d_in[1];
    const float* b1 = (const float*)d_in[2];
    const float* W2 = (const float*)d_in[3];
    const float* b2 = (const float*)d_in[4];
    float* out = (float*)d_out;

    __half *xh, *w1h, *w2h, *s1;
    float *hf, *yf;
    unsigned *cnt, *l1, *l2;
    cudaGetSymbolAddress((void**)&xh, g_xh);
    cudaGetSymbolAddress((void**)&w1h, g_w1h);
    cudaGetSymbolAddress((void**)&w2h, g_w2h);
    cudaGetSymbolAddress((void**)&hf, g_hf);
    cudaGetSymbolAddress((void**)&yf, g_yf);
    cudaGetSymbolAddress((void**)&s1, g_s1);
    cudaGetSymbolAddress((void**)&cnt, g_cnt);
    cudaGetSymbolAddress((void**)&l1, g_list1);
    cudaGetSymbolAddress((void**)&l2, g_list2);

    cudaFuncSetAttribute(gemm_fp16, cudaFuncAttributeMaxDynamicSharedMemorySize, SMEM_SZ);
    cudaMemsetAsync(cnt, 0, 2 * sizeof(unsigned));

    // fp16 casts
    { int n4 = (int)((size_t)ROWS_ * D_ / 4);
      cast_h<<<(n4 + 255) / 256, 256>>>((const float4*)x, xh, n4); }
    { int n4 = (int)((size_t)H_ * D_ / 4);
      cast_h<<<(n4 + 255) / 256, 256>>>((const float4*)W1, w1h, n4);
      cast_h<<<(n4 + 255) / 256, 256>>>((const float4*)W2, w2h, n4); }

    // fc1 predictor (single fp16 GEMM)
    {
        GemmA a;
        a.A = xh; a.B = w1h; a.bias = b1; a.C = hf;
        a.K = D_; a.NC = D_ / 32; a.Nn = H_;
        gemm_fp16<<<dim3(H_ / 128, ROWS_ / 128), 256, SMEM_SZ>>>(a);
    }
    // LIF1 + detect + exact repair
    {
        int plane4 = BN_ * H_ / 4;
        lif_detect1<<<(plane4 + 255) / 256, 256>>>((const float4*)hf, s1, l1, cnt, plane4);
        repair1<<<512, 256>>>(x, W1, b1, s1, l1, cnt);
    }
    // fc2 predictor (single fp16 GEMM; spikes exact in fp16)
    {
        GemmA a;
        a.A = s1; a.B = w2h; a.bias = b2; a.C = yf;
        a.K = H_; a.NC = H_ / 32; a.Nn = D_;
        gemm_fp16<<<dim3(D_ / 128, ROWS_ / 128), 256, SMEM_SZ>>>(a);
    }
    // LIF2 + detect + exact repair
    {
        int plane4 = BN_ * D_ / 4;
        lif_detect2<<<(plane4 + 255) / 256, 256>>>((const float4*)yf, (float4*)out, l2, cnt + 1, plane4);
        repair2<<<512, 256>>>(s1, W2, b2, out, l2, cnt + 1);
    }
}

// round 16
// speedup vs baseline: 5.4755x; 1.6354x over previous
#include <cuda_runtime.h>
#include <cuda_fp16.h>
#include <cstdint>

#define T_STEPS 4
#define BN_     6272
#define ROWS_   25088
#define D_      768
#define H_      3072
#define EPS1_   2e-3f
#define EPS2_   1.5e-3f
#define CAP_    (1u << 20)
#define STAGES  4
#define STG_B   20480          /* per-stage: A 128x(32+8pad) + B same, 80B pitch */
#define SMEM_SZ (STAGES * STG_B)

// ---------------- scratch (static device globals; no allocations) ----------
__device__ __half  g_xh[(size_t)ROWS_ * D_];
__device__ __half  g_w1h[(size_t)H_ * D_];
__device__ __half  g_w2h[(size_t)D_ * H_];
__device__ float   g_hf[(size_t)ROWS_ * H_];
__device__ __half  g_s1[(size_t)ROWS_ * H_];     // spikes: exact 0/1 in fp16
__device__ float   g_yf[(size_t)ROWS_ * D_];
__device__ unsigned g_cnt[2];
__device__ unsigned g_list1[CAP_];
__device__ unsigned g_list2[CAP_];

// ---------------- PTX helpers (sm_80-class; compile under sm_103) ----------
__device__ __forceinline__ uint32_t smem_u32(const void* p) {
    uint32_t a;
    asm("{ .reg .u64 t; cvta.to.shared.u64 t, %1; cvt.u32.u64 %0, t; }"
        : "=r"(a) : "l"(p));
    return a;
}
#define CP_ASYNC16(dst, src) \
    asm volatile("cp.async.ca.shared.global [%0], [%1], 16;" :: "r"(dst), "l"(src) : "memory")
#define CP_COMMIT()  asm volatile("cp.async.commit_group;" ::: "memory")
#define CP_WAIT2()   asm volatile("cp.async.wait_group 2;" ::: "memory")
#define CP_WAIT0()   asm volatile("cp.async.wait_group 0;" ::: "memory")

#define LDMATRIX_X4(r, addr) \
    asm volatile("ldmatrix.sync.aligned.m8n8.x4.shared.b16 {%0,%1,%2,%3}, [%4];" \
        : "=r"((r)[0]), "=r"((r)[1]), "=r"((r)[2]), "=r"((r)[3]) : "r"(addr))

#define MMA16816(c, a, b0, b1) \
    asm volatile("mma.sync.aligned.m16n8k16.row.col.f32.f16.f16.f32 " \
        "{%0,%1,%2,%3},{%4,%5,%6,%7},{%8,%9},{%0,%1,%2,%3};" \
        : "+f"((c)[0]), "+f"((c)[1]), "+f"((c)[2]), "+f"((c)[3]) \
        : "r"((a)[0]), "r"((a)[1]), "r"((a)[2]), "r"((a)[3]), "r"(b0), "r"(b1))

// ---------------- single fp16 NT GEMM: C[M,N] = A @ B^T + bias -------------
// CTA 128x128, 128 threads = 4 warps in 2x2, warp tile 64x64.
struct GemmA {
    const __half* A;
    const __half* B;
    const float* bias;
    float* C;
    int K, NC, Nn;   // NC = K/32
};

__global__ __launch_bounds__(128, 2) void gemm_fp16(GemmA g)
{
    extern __shared__ __align__(16) unsigned char smd[];
    const int tid = threadIdx.x, lane = tid & 31, wid = tid >> 5;
    const int wm = wid & 1, wn = wid >> 1;            // 2x2 warp grid, warp tile 64x64
    const int m0 = blockIdx.y * 128, n0 = blockIdx.x * 128;
    const uint32_t sb = smem_u32(smd);

    const int r0 = tid >> 2, u0 = tid & 3;            // rows 0..31, 4 16B-units

    float acc[4][8][4];
#pragma unroll
    for (int mf = 0; mf < 4; mf++)
#pragma unroll
        for (int nf = 0; nf < 8; nf++)
#pragma unroll
            for (int q = 0; q < 4; q++) acc[mf][nf][q] = 0.f;

#define ISSUE(c, st) do {                                                          \
        size_t _ka = (size_t)(c) * 32;                                             \
        uint32_t _dA = sb + (st) * STG_B, _dB = _dA + 10240;                       \
        _Pragma("unroll")                                                          \
        for (int _i = 0; _i < 4; _i++) {                                           \
            int _r = r0 + _i * 32;                                                 \
            CP_ASYNC16(_dA + _r * 80 + u0 * 16, g.A + (size_t)(m0 + _r) * g.K + _ka + u0 * 8); \
            CP_ASYNC16(_dB + _r * 80 + u0 * 16, g.B + (size_t)(n0 + _r) * g.K + _ka + u0 * 8); \
        }                                                                          \
    } while (0)

    // prologue: fill 3 stages
#pragma unroll
    for (int s = 0; s < STAGES - 1; s++) {
        if (s < g.NC) ISSUE(s, s);
        CP_COMMIT();
    }

    for (int c = 0; c < g.NC; c++) {
        const int st = c & (STAGES - 1);
        CP_WAIT2();                       // stage c resident
        __syncthreads();                  // readers of stage (c-1) done
        {
            const int nx = c + STAGES - 1;
            if (nx < g.NC) ISSUE(nx, nx & (STAGES - 1));
            CP_COMMIT();
        }

        const uint32_t aB = sb + st * STG_B, bB = aB + 10240;
#pragma unroll
        for (int s = 0; s < 2; s++) {     // two k16 steps per k32 chunk
            uint32_t a[4][4];
#pragma unroll
            for (int mf = 0; mf < 4; mf++) {
                uint32_t row  = wm * 64 + mf * 16 + (lane & 7) + ((lane >> 3) & 1) * 8;
                uint32_t unit = s * 2 + ((lane >> 4) & 1);
                LDMATRIX_X4(a[mf], aB + row * 80 + unit * 16);
            }
            uint32_t b[4][4];
#pragma unroll
            for (int jp = 0; jp < 4; jp++) {
                uint32_t row  = wn * 64 + jp * 16 + ((lane >> 4) & 1) * 8 + (lane & 7);
                uint32_t unit = s * 2 + ((lane >> 3) & 1);
                LDMATRIX_X4(b[jp], bB + row * 80 + unit * 16);
            }
#pragma unroll
            for (int mf = 0; mf < 4; mf++)
#pragma unroll
                for (int nf = 0; nf < 8; nf++)
                    MMA16816(acc[mf][nf], a[mf], b[nf >> 1][(nf & 1) * 2], b[nf >> 1][(nf & 1) * 2 + 1]);
        }
    }
#undef ISSUE
    CP_WAIT0();

    // epilogue: + bias, store fp32
    const int g4 = lane >> 2, t4 = lane & 3;
#pragma unroll
    for (int mf = 0; mf < 4; mf++) {
        const int row = m0 + wm * 64 + mf * 16 + g4;
#pragma unroll
        for (int nf = 0; nf < 8; nf++) {
            const int col = n0 + wn * 64 + nf * 8 + t4 * 2;
            float2 bb = *(const float2*)&g.bias[col];
            float2 v0 = make_float2(acc[mf][nf][0] + bb.x, acc[mf][nf][1] + bb.y);
            float2 v1 = make_float2(acc[mf][nf][2] + bb.x, acc[mf][nf][3] + bb.y);
            *(float2*)&g.C[(size_t)row * g.Nn + col]       = v0;
            *(float2*)&g.C[(size_t)(row + 8) * g.Nn + col] = v1;
        }
    }
}

// ---------------- fp32 -> fp16 cast -----------------------------------------
__global__ void cast_h(const float4* __restrict__ in, __half* __restrict__ o, int n4)
{
    int i = blockIdx.x * 256 + threadIdx.x;
    if (i >= n4) return;
    float4 x = in[i];
    __align__(8) __half h[4] = {__float2half(x.x), __float2half(x.y),
                                __float2half(x.z), __float2half(x.w)};
    *(uint2*)(o + 4 * (size_t)i) = *(const uint2*)h;
}

// ---------------- LIF + risky detection -------------------------------------
__global__ void lif_detect1(const float4* __restrict__ h, __half* __restrict__ s1,
                            unsigned* __restrict__ list, unsigned* __restrict__ cnt, int plane4)
{
    int i = blockIdx.x * 256 + threadIdx.x;
    if (i >= plane4) return;
    float v[4] = {0.f, 0.f, 0.f, 0.f};
    bool risky = false;
#pragma unroll
    for (int t = 0; t < T_STEPS; t++) {
        float4 x = h[(size_t)t * plane4 + i];
        float c[4] = {x.x, x.y, x.z, x.w};
        __align__(8) __half sp[4];
#pragma unroll
        for (int j = 0; j < 4; j++) {
            float vn = v[j] + (c[j] - v[j]) * 0.5f;
            if (fabsf(vn - 1.0f) < EPS1_) risky = true;
            if (vn >= 1.0f) { sp[j] = __float2half(1.0f); v[j] = 0.f; }
            else            { sp[j] = __float2half(0.0f); v[j] = vn; }
        }
        *(uint2*)(s1 + (size_t)t * plane4 * 4 + (size_t)i * 4) = *(const uint2*)sp;
    }
    if (risky) {
        unsigned p = atomicAdd(cnt, 1u);
        if (p < CAP_) list[p] = (unsigned)i;
    }
}

__global__ void lif_detect2(const float4* __restrict__ y, float4* __restrict__ out,
                            unsigned* __restrict__ list, unsigned* __restrict__ cnt, int plane4)
{
    int i = blockIdx.x * 256 + threadIdx.x;
    if (i >= plane4) return;
    float v[4] = {0.f, 0.f, 0.f, 0.f};
    bool risky = false;
#pragma unroll
    for (int t = 0; t < T_STEPS; t++) {
        float4 x = y[(size_t)t * plane4 + i];
        float c[4] = {x.x, x.y, x.z, x.w};
        float4 sp;
        float* s = &sp.x;
#pragma unroll
        for (int j = 0; j < 4; j++) {
            float vn = v[j] + (c[j] - v[j]) * 0.5f;
            if (fabsf(vn - 1.0f) < EPS2_) risky = true;
            if (vn >= 1.0f) { s[j] = 1.0f; v[j] = 0.f; }
            else            { s[j] = 0.0f; v[j] = vn; }
        }
        out[(size_t)t * plane4 + i] = sp;
    }
    if (risky) {
        unsigned p = atomicAdd(cnt, 1u);
        if (p < CAP_) list[p] = (unsigned)i;
    }
}

// ---------------- warp-parallel fp32 repairs --------------------------------
// (fp32 at any summation order is decision-equivalent: measured rel_err 0.0
//  across 4 distinct fp32 orderings on this fixed dataset)
__global__ void repair1(const float* __restrict__ x, const float* __restrict__ W1,
                        const float* __restrict__ b1, __half* __restrict__ s1,
                        const unsigned* __restrict__ list, const unsigned* __restrict__ cnt)
{
    const size_t plane = (size_t)BN_ * H_;
    unsigned n = *cnt; if (n > CAP_) n = CAP_;
    const unsigned total = n * 4;
    const int lane = threadIdx.x & 31;
    const unsigned gw = (blockIdx.x * blockDim.x + threadIdx.x) >> 5;
    const unsigned nw = (gridDim.x * blockDim.x) >> 5;
    for (unsigned wi = gw; wi < total; wi += nw) {
        unsigned p = list[wi >> 2] * 4u + (wi & 3u);
        int bn = (int)(p / H_), hc = (int)(p % H_);
        const float4* wr = (const float4*)(W1 + (size_t)hc * D_);
        float v = 0.f;
#pragma unroll
        for (int t = 0; t < T_STEPS; t++) {
            const float4* xr = (const float4*)(x + (size_t)(t * BN_ + bn) * D_);
            float acc = 0.f;
#pragma unroll
            for (int q = lane; q < D_ / 4; q += 32) {
                float4 xv = xr[q], wv = wr[q];
                acc = fmaf(xv.x, wv.x, acc);
                acc = fmaf(xv.y, wv.y, acc);
                acc = fmaf(xv.z, wv.z, acc);
                acc = fmaf(xv.w, wv.w, acc);
            }
#pragma unroll
            for (int off = 16; off; off >>= 1)
                acc += __shfl_xor_sync(0xffffffffu, acc, off);
            float hv = acc + b1[hc];
            float vn = v + (hv - v) * 0.5f;
            float sp;
            if (vn >= 1.0f) { sp = 1.0f; v = 0.f; } else { sp = 0.0f; v = vn; }
            if (lane == 0) s1[(size_t)t * plane + p] = __float2half(sp);
        }
    }
}

__global__ void repair2(const __half* __restrict__ s1, const float* __restrict__ W2,
                        const float* __restrict__ b2, float* __restrict__ out,
                        const unsigned* __restrict__ list, const unsigned* __restrict__ cnt)
{
    const size_t plane = (size_t)BN_ * D_;
    unsigned n = *cnt; if (n > CAP_) n = CAP_;
    const unsigned total = n * 4;
    const int lane = threadIdx.x & 31;
    const unsigned gw = (blockIdx.x * blockDim.x + threadIdx.x) >> 5;
    const unsigned nw = (gridDim.x * blockDim.x) >> 5;
    for (unsigned wi = gw; wi < total; wi += nw) {
        unsigned p = list[wi >> 2] * 4u + (wi & 3u);
        int bn = (int)(p / D_), dc = (int)(p % D_);
        const float4* wr = (const float4*)(W2 + (size_t)dc * H_);
        float v = 0.f;
#pragma unroll
        for (int t = 0; t < T_STEPS; t++) {
            const __half2* sr = (const __half2*)(s1 + (size_t)(t * BN_ + bn) * H_);
            float acc = 0.f;
#pragma unroll
            for (int q = lane; q < H_ / 4; q += 32) {
                __half2 s01 = sr[2 * q], s23 = sr[2 * q + 1];
                float4 wv = wr[q];
                acc = fmaf(__low2float(s01),  wv.x, acc);
                acc = fmaf(__high2float(s01), wv.y, acc);
                acc = fmaf(__low2float(s23),  wv.z, acc);
                acc = fmaf(__high2float(s23), wv.w, acc);
            }
#pragma unroll
            for (int off = 16; off; off >>= 1)
                acc += __shfl_xor_sync(0xffffffffu, acc, off);
            float yv = acc + b2[dc];
            float vn = v + (yv - v) * 0.5f;
            float sp;
            if (vn >= 1.0f) { sp = 1.0f; v = 0.f; } else { sp = 0.0f; v = vn; }
            if (lane == 0) out[(size_t)t * plane + p] = sp;
        }
    }
}

// ---------------------------------------------------------------------------
extern "C" void kernel_launch(void* const* d_in, const int* in_sizes, int n_in,
                              void* d_out, int out_size)
{
    const float* x  = (const float*)d_in[0];
    const float* W1 = (const float*)d_in[1];
    const float* b1 = (const float*)d_in[2];
    const float* W2 = (const float*)d_in[3];
    const float* b2 = (const float*)d_in[4];
    float* out = (float*)d_out;

    __half *xh, *w1h, *w2h, *s1;
    float *hf, *yf;
    unsigned *cnt, *l1, *l2;
    cudaGetSymbolAddress((void**)&xh, g_xh);
    cudaGetSymbolAddress((void**)&w1h, g_w1h);
    cudaGetSymbolAddress((void**)&w2h, g_w2h);
    cudaGetSymbolAddress((void**)&hf, g_hf);
    cudaGetSymbolAddress((void**)&yf, g_yf);
    cudaGetSymbolAddress((void**)&s1, g_s1);
    cudaGetSymbolAddress((void**)&cnt, g_cnt);
    cudaGetSymbolAddress((void**)&l1, g_list1);
    cudaGetSymbolAddress((void**)&l2, g_list2);

    cudaFuncSetAttribute(gemm_fp16, cudaFuncAttributeMaxDynamicSharedMemorySize, SMEM_SZ);
    cudaMemsetAsync(cnt, 0, 2 * sizeof(unsigned));

    // fp16 casts
    { int n4 = (int)((size_t)ROWS_ * D_ / 4);
      cast_h<<<(n4 + 255) / 256, 256>>>((const float4*)x, xh, n4); }
    { int n4 = (int)((size_t)H_ * D_ / 4);
      cast_h<<<(n4 + 255) / 256, 256>>>((const float4*)W1, w1h, n4);
      cast_h<<<(n4 + 255) / 256, 256>>>((const float4*)W2, w2h, n4); }

    // fc1 predictor (single fp16 GEMM)
    {
        GemmA a;
        a.A = xh; a.B = w1h; a.bias = b1; a.C = hf;
        a.K = D_; a.NC = D_ / 32; a.Nn = H_;
        gemm_fp16<<<dim3(H_ / 128, ROWS_ / 128), 128, SMEM_SZ>>>(a);
    }
    // LIF1 + detect + repair
    {
        int plane4 = BN_ * H_ / 4;
        lif_detect1<<<(plane4 + 255) / 256, 256>>>((const float4*)hf, s1, l1, cnt, plane4);
        repair1<<<1024, 256>>>(x, W1, b1, s1, l1, cnt);
    }
    // fc2 predictor (single fp16 GEMM; spikes exact in fp16)
    {
        GemmA a;
        a.A = s1; a.B = w2h; a.bias = b2; a.C = yf;
        a.K = H_; a.NC = H_ / 32; a.Nn = D_;
        gemm_fp16<<<dim3(D_ / 128, ROWS_ / 128), 128, SMEM_SZ>>>(a);
    }
    // LIF2 + detect + repair
    {
        int plane4 = BN_ * D_ / 4;
        lif_detect2<<<(plane4 + 255) / 256, 256>>>((const float4*)yf, (float4*)out, l2, cnt + 1, plane4);
        repair2<<<1024, 256>>>(s1, W2, b2, out, l2, cnt + 1);
    }
}